// round 6
// baseline (speedup 1.0000x reference)
#include <cuda_runtime.h>
#include <cuda_fp16.h>
#include <math.h>

// Problem constants (fixed by reference)
#define B_     32
#define L_     16000
#define CF_    5
#define LN2F   0.69314718055994531f
#define HLN2F  0.34657359027997264f     // 0.5*ln2

// Tiling: 56 loci per CTA (even => exact symmetric split; <=64 for bitmasks)
#define LC     56
#define NB     286
#define SROW   33                        // smem row stride (elements)

#define SCALE_JS   4294967296.0f         // 2^32
#define ISCALE_JS  (1.0 / 4294967296.0)
#define SCALE_CE   1048576.0f            // 2^20
#define ISCALE_CE  (1.0 / 1048576.0)

// ---- scratch (device globals, zero-initialized at module load) ----
__device__ long long      g_js_acc[1024];      // fixed-point js per pair
__device__ int            g_cnt_acc[1024];     // exact mask counts per pair
__device__ long long      g_ce_acc;            // fixed-point CE sum
__device__ int            g_nm_tot[8];         // per-group nonmiss locus count
__device__ unsigned int   g_done;              // CTA completion counter
__device__ float          g_pred[L_ * 8];      // [locus][group] pred_alt
__device__ unsigned char  g_altp[L_ * 8];      // alt_cnt | (nonmiss<<4)

// ============================================================================
// Single mega-kernel: staging + CE + r2 partials + bitmask pairwise JS,
// then last-CTA finalization (r2, evo combine, output, accumulator reset).
// ============================================================================
__global__ void __launch_bounds__(1024) k_all(
    const float4* __restrict__ logits4,   // (B, L) float4 (C=4)
    const float4* __restrict__ prob4,
    const float*  __restrict__ ytrue,     // (B, L, 5)
    const float*  __restrict__ yevo,      // (B, B)
    float*        __restrict__ out)
{
    __shared__ uint2              s_p [LC * SROW];   // 4 x fp16 clamped prob
    __shared__ float              s_h [LC * SROW];   // h' = sum p*log2p + sum p
    __shared__ unsigned char      s_lab[LC * SROW];  // labels
    __shared__ unsigned long long s_lm[32 * 4];      // label bitmask [batch][class]
    __shared__ int                s_nm[8];
    __shared__ float              s_ce[32];
    __shared__ int                s_last;
    __shared__ float              s_f[1024];         // finalize: js stage
    __shared__ int                s_c[1024];         // finalize: cnt stage

    const int tid  = threadIdx.x;
    const int lane = tid & 31;
    const int w    = tid >> 5;
    const int l0   = blockIdx.x * LC;
    const int nloc = min(LC, L_ - l0);     // 56 or 40 (even)
    const int n32  = nloc * 32;

    if (tid < 8) s_nm[tid] = 0;
    __syncthreads();

    // ---- staging: coalesced global loads ----
    float ce_acc = 0.0f;
    for (int e = tid; e < n32; e += 1024) {
        int i  = e / nloc;
        int ll = e - i * nloc;
        size_t gi = (size_t)i * L_ + l0 + ll;

        const float* yt = ytrue + gi * CF_;
        float lf = yt[1] + 2.0f * yt[2] + 3.0f * yt[3] + 4.0f * yt[4];
        int lbl = (int)(lf + 0.5f);

        float4 lg = logits4[gi];
        float m  = fmaxf(fmaxf(lg.x, lg.y), fmaxf(lg.z, lg.w));
        float se = __expf(lg.x - m) + __expf(lg.y - m) +
                   __expf(lg.z - m) + __expf(lg.w - m);
        if (lbl != 4) {
            float sel = (lbl == 0) ? lg.x : (lbl == 1) ? lg.y : (lbl == 2) ? lg.z : lg.w;
            ce_acc += (m + LN2F * __log2f(se)) - sel;
        }

        float4 p = prob4[gi];
        float a = fmaxf(p.x, 1e-7f), b = fmaxf(p.y, 1e-7f);
        float c = fmaxf(p.z, 1e-7f), d = fmaxf(p.w, 1e-7f);
        float hp = a * __log2f(a) + b * __log2f(b) +
                   c * __log2f(c) + d * __log2f(d) + (a + b + c + d);

        __half2 p01 = __floats2half2_rn(a, b);
        __half2 p23 = __floats2half2_rn(c, d);
        int idx = ll * SROW + i;
        s_p[idx]   = make_uint2(reinterpret_cast<unsigned&>(p01),
                                reinterpret_cast<unsigned&>(p23));
        s_h[idx]   = hp;
        s_lab[idx] = (unsigned char)lbl;
    }

    // CE: warp partials -> one deterministic int atomic per CTA
#pragma unroll
    for (int o = 16; o > 0; o >>= 1) ce_acc += __shfl_xor_sync(0xFFFFFFFFu, ce_acc, o);
    if (lane == 0) s_ce[w] = ce_acc;
    __syncthreads();
    if (tid == 0) {
        float s = 0.0f;
#pragma unroll
        for (int k = 0; k < 32; ++k) s += s_ce[k];
        atomicAdd((unsigned long long*)&g_ce_acc,
                  (unsigned long long)(long long)(s * SCALE_CE));
    }

    // ---- label bitmasks per (batch, class) ----
    if (tid < 128) {
        int b = tid >> 2, c = tid & 3;
        unsigned long long m = 0ull;
        for (int ll = 0; ll < nloc; ++ll)
            m |= (unsigned long long)(s_lab[ll * SROW + b] == c) << ll;
        s_lm[tid] = m;
    }

    // ---- r2 group partials ----
    if (tid < nloc * 8) {
        int g  = tid & 7;
        int ll = tid >> 3;
        int base = ll * SROW + g * 4;
        float pred = 0.0f;
        int alt = 0, nm = 0;
#pragma unroll
        for (int q = 0; q < 4; ++q) {
            uint2 u = s_p[base + q];
            float2 f01 = __half22float2(reinterpret_cast<__half2&>(u.x));
            float2 f23 = __half22float2(reinterpret_cast<__half2&>(u.y));
            pred += f01.y + f23.x + f23.y;
            int lb = s_lab[base + q];
            alt += (lb >= 1 && lb <= 3);
            nm  |= (lb != 4);
        }
        int l = l0 + ll;
        g_pred[l * 8 + g] = 0.25f * pred;
        g_altp[l * 8 + g] = (unsigned char)(alt | (nm << 4));
        if (nm) atomicAdd(&s_nm[g], 1);
    }
    __syncthreads();
    if (tid < 8) atomicAdd(&g_nm_tot[tid], s_nm[tid]);

    // ---- pairwise JS via bitmask compaction ----
    {
        const int i = w;
        const int j = lane;
        const int H = nloc >> 1;

        unsigned long long pm =
            (s_lm[i * 4 + 0] & s_lm[j * 4 + 0]) |
            (s_lm[i * 4 + 1] & s_lm[j * 4 + 1]) |
            (s_lm[i * 4 + 2] & s_lm[j * 4 + 2]) |
            (s_lm[i * 4 + 3] & s_lm[j * 4 + 3]);
        unsigned long long lowm = (1ull << H) - 1ull;
        pm = (j < i) ? (pm & ~lowm) : (pm & lowm);   // symmetric split

        int   cnt = __popcll(pm);
        float js  = 0.0f;
        while (pm) {
            int k = __ffsll((long long)pm) - 1;
            pm &= pm - 1ull;
            const int row = k * SROW;
            uint2 ui = s_p[row + i];               // broadcast
            uint2 uj = s_p[row + j];
            float hsum = s_h[row + i] + s_h[row + j];
            __half2 s01 = __hadd2(reinterpret_cast<__half2&>(ui.x),
                                  reinterpret_cast<__half2&>(uj.x));
            __half2 s23 = __hadd2(reinterpret_cast<__half2&>(ui.y),
                                  reinterpret_cast<__half2&>(uj.y));
            float f0 = __low2float(s01), f1 = __high2float(s01);
            float f2 = __low2float(s23), f3 = __high2float(s23);
            float slog2 = f0 * __log2f(f0) + f1 * __log2f(f1) +
                          f2 * __log2f(f2) + f3 * __log2f(f3);
            js += hsum - slog2;
        }
        atomicAdd((unsigned long long*)&g_js_acc[tid],
                  (unsigned long long)(long long)(js * SCALE_JS));
        if (cnt) atomicAdd(&g_cnt_acc[tid], cnt);
    }

    // ---- completion protocol ----
    __threadfence();
    __syncthreads();
    if (tid == 0) {
        unsigned old = atomicAdd(&g_done, 1u);
        s_last = (old == NB - 1);
    }
    __syncthreads();
    if (!s_last) return;
    __threadfence();

    // ================= last CTA: finalization =================
    // nm totals -> smem
    if (tid < 8) s_nm[tid] = g_nm_tot[tid];
    __syncthreads();

    // r2 over (locus, group), float4-vectorized
    float r2acc = 0.0f;
    const float4* pred4 = (const float4*)g_pred;
    const unsigned* altp4 = (const unsigned*)g_altp;
    for (int idx4 = tid; idx4 < (L_ * 8) / 4; idx4 += 1024) {
        float4 pr = pred4[idx4];
        unsigned ap = altp4[idx4];
        int gbase = (idx4 & 1) * 4;
        float prv[4] = {pr.x, pr.y, pr.z, pr.w};
#pragma unroll
        for (int q = 0; q < 4; ++q) {
            unsigned char pk = (ap >> (q * 8)) & 0xFF;
            float cntg = fmaxf(4.0f * (float)s_nm[gbase + q], 1.0f);
            float alt = (float)(pk & 15);
            bool nonmiss = (pk & 16) != 0;
            float af2 = nonmiss ? (alt / cntg) : 0.5f;
            if (nonmiss && af2 != 0.0f && af2 != 1.0f) {
                float den = fmaxf(af2 * (1.0f - af2), 0.01f);
                float dd  = prv[q] - af2;
                r2acc += dd * dd / den;
            }
        }
    }

    // evo: combine symmetric halves via transpose
    s_f[tid] = (float)((double)g_js_acc[tid] * ISCALE_JS);
    s_c[tid] = g_cnt_acc[tid];
    __syncthreads();
    const int tT = (tid & 31) * 32 + (tid >> 5);
    float jsv = HLN2F * (s_f[tid] + s_f[tT]) /
                fmaxf((float)(s_c[tid] + s_c[tT]), 1.0f);
    float wgt = __expf(-yevo[tid]);
    float rs = wgt;
#pragma unroll
    for (int o = 16; o > 0; o >>= 1) rs += __shfl_xor_sync(0xFFFFFFFFu, rs, o);
    float term = (wgt / (rs + 1e-8f)) * jsv;

    // block-reduce term + r2
#pragma unroll
    for (int o = 16; o > 0; o >>= 1) {
        term  += __shfl_xor_sync(0xFFFFFFFFu, term,  o);
        r2acc += __shfl_xor_sync(0xFFFFFFFFu, r2acc, o);
    }
    __syncthreads();                // s_f/s_c reads complete before reuse
    if (lane == 0) { s_f[w] = term; s_f[32 + w] = r2acc; }
    __syncthreads();
    if (tid == 0) {
        float evo = 0.0f, r2 = 0.0f;
#pragma unroll
        for (int k = 0; k < 32; ++k) { evo += s_f[k]; r2 += s_f[32 + k]; }
        float ce = (float)((double)g_ce_acc * ISCALE_CE);
        if (!isfinite(evo)) evo = 0.0f;
        out[0] = ce - 0.125f * r2 + evo;   // r2_loss = -sum*GS/B
    }

    // reset accumulators for the next graph replay
    __syncthreads();
    g_js_acc[tid] = 0ll;
    g_cnt_acc[tid] = 0;
    if (tid < 8) g_nm_tot[tid] = 0;
    if (tid == 0) { g_ce_acc = 0ll; g_done = 0u; }
}

extern "C" void kernel_launch(void* const* d_in, const int* in_sizes, int n_in,
                              void* d_out, int out_size)
{
    const float* logits = (const float*)d_in[0];
    const float* prob   = (const float*)d_in[1];
    const float* ytrue  = (const float*)d_in[2];
    const float* yevo   = (const float*)d_in[3];

    k_all<<<NB, 1024>>>((const float4*)logits, (const float4*)prob,
                        ytrue, yevo, (float*)d_out);
}

// round 7
// speedup vs baseline: 2.0716x; 2.0716x over previous
#include <cuda_runtime.h>
#include <cuda_fp16.h>
#include <math.h>

// Problem constants (fixed by reference)
#define B_     32
#define L_     16000
#define CF_    5
#define LN2F   0.69314718055994531f
#define HLN2F  0.34657359027997264f   // 0.5*ln2

// k2 tiling: 56 loci per CTA (even => exact symmetric split). 286 CTAs.
#define LC     56
#define NB     286
#define SROW   33                      // smem row stride (elements)

#define SCALE_JS   4294967296.0f       // 2^32
#define ISCALE_JS  (1.0 / 4294967296.0)
#define SCALE_S    1048576.0f          // 2^20 (ce, r2)
#define ISCALE_S   (1.0 / 1048576.0)

// ---- scratch (device globals, zero-initialized at module load) ----
__device__ float          g_js_part [NB * 1024];   // [cta][pair] coalesced
__device__ float          g_cnt_part[NB * 1024];
__device__ float          g_pred[L_ * 8];          // [locus][group]
__device__ unsigned char  g_altp[L_ * 8];          // alt_cnt | (nonmiss<<4)
__device__ int            g_nm_part[NB * 8];       // [cta][group]
__device__ float          g_ce_part[NB * 32];      // [cta][warp]
__device__ long long      g_js_acc[1024];          // fixed-point per pair
__device__ int            g_cnt_acc[1024];
__device__ long long      g_ce_acc, g_r2_acc;
__device__ unsigned int   g_done;

// ============================================================================
// k2: fused staging (labels, CE, h', fp16 probs) + symmetric pairwise JS
// (identical to the proven R5 kernel)
// ============================================================================
__global__ void __launch_bounds__(1024) k2_mega(
    const float4* __restrict__ logits4,   // (B, L) float4 (C=4)
    const float4* __restrict__ prob4,
    const float*  __restrict__ ytrue)     // (B, L, 5)
{
    __shared__ uint2    s_p[LC * SROW];   // 4 x fp16 clamped prob
    __shared__ unsigned s_m[LC * SROW];   // (bf16 h' << 16) | label
    __shared__ int      s_nm[8];

    const int tid  = threadIdx.x;
    const int lane = tid & 31;
    const int l0   = blockIdx.x * LC;
    const int nloc = min(LC, L_ - l0);     // 56 or 40 (even)
    const int n32  = nloc * 32;

    if (tid < 8) s_nm[tid] = 0;
    __syncthreads();

    // ---- staging: coalesced global loads ----
    float ce_acc = 0.0f;
    for (int e = tid; e < n32; e += 1024) {
        int i  = e / nloc;
        int ll = e - i * nloc;
        size_t gi = (size_t)i * L_ + l0 + ll;

        const float* yt = ytrue + gi * CF_;
        float lf = yt[1] + 2.0f * yt[2] + 3.0f * yt[3] + 4.0f * yt[4];
        int lbl = (int)(lf + 0.5f);

        float4 lg = logits4[gi];
        float m  = fmaxf(fmaxf(lg.x, lg.y), fmaxf(lg.z, lg.w));
        float se = __expf(lg.x - m) + __expf(lg.y - m) +
                   __expf(lg.z - m) + __expf(lg.w - m);
        if (lbl != 4) {
            float sel = (lbl == 0) ? lg.x : (lbl == 1) ? lg.y : (lbl == 2) ? lg.z : lg.w;
            ce_acc += (m + LN2F * __log2f(se)) - sel;
        }

        float4 p = prob4[gi];
        float a = fmaxf(p.x, 1e-7f), b = fmaxf(p.y, 1e-7f);
        float c = fmaxf(p.z, 1e-7f), d = fmaxf(p.w, 1e-7f);
        float hp = a * __log2f(a) + b * __log2f(b) +
                   c * __log2f(c) + d * __log2f(d) + (a + b + c + d);
        unsigned hb = (__float_as_uint(hp) + 0x8000u) & 0xFFFF0000u;

        __half2 p01 = __floats2half2_rn(a, b);
        __half2 p23 = __floats2half2_rn(c, d);
        int idx = ll * SROW + i;
        s_p[idx] = make_uint2(reinterpret_cast<unsigned&>(p01),
                              reinterpret_cast<unsigned&>(p23));
        s_m[idx] = hb | (unsigned)lbl;
    }

#pragma unroll
    for (int o = 16; o > 0; o >>= 1) ce_acc += __shfl_xor_sync(0xFFFFFFFFu, ce_acc, o);
    if (lane == 0) g_ce_part[blockIdx.x * 32 + (tid >> 5)] = ce_acc;

    __syncthreads();

    // ---- r2 group partials from staged smem ----
    if (tid < nloc * 8) {
        int g  = tid & 7;
        int ll = tid >> 3;
        int base = ll * SROW + g * 4;
        float pred = 0.0f;
        int alt = 0, nm = 0;
#pragma unroll
        for (int q = 0; q < 4; ++q) {
            uint2 u = s_p[base + q];
            float2 f01 = __half22float2(reinterpret_cast<__half2&>(u.x));
            float2 f23 = __half22float2(reinterpret_cast<__half2&>(u.y));
            pred += f01.y + f23.x + f23.y;
            int lb = s_m[base + q] & 0xFF;
            alt += (lb >= 1 && lb <= 3);
            nm  |= (lb != 4);
        }
        int l = l0 + ll;
        g_pred[l * 8 + g] = 0.25f * pred;
        g_altp[l * 8 + g] = (unsigned char)(alt | (nm << 4));
        if (nm) atomicAdd(&s_nm[g], 1);
    }
    __syncthreads();
    if (tid < 8) g_nm_part[blockIdx.x * 8 + tid] = s_nm[tid];

    // ---- symmetric pairwise JS: (i,j) j>=i does [0,H); j<i does [H,nloc) ----
    const int i = tid >> 5;
    const int j = lane;
    const int H = nloc >> 1;
    const int start = (j < i) ? H : 0;

    float js = 0.0f, cnt = 0.0f;
#pragma unroll 2
    for (int k = 0; k < H; ++k) {
        const int row = (start + k) * SROW;
        unsigned wi = s_m[row + i];           // broadcast
        unsigned li = wi & 0xFFu;
        if (li == 4u) continue;               // warp-uniform skip (20% of loci)
        unsigned wj = s_m[row + j];
        float msk = ((wj & 0xFFu) == li) ? 1.0f : 0.0f;
        uint2 ui = s_p[row + i];              // broadcast
        uint2 uj = s_p[row + j];
        __half2 s01 = __hadd2(reinterpret_cast<__half2&>(ui.x),
                              reinterpret_cast<__half2&>(uj.x));
        __half2 s23 = __hadd2(reinterpret_cast<__half2&>(ui.y),
                              reinterpret_cast<__half2&>(uj.y));
        float2 f01 = __half22float2(s01);
        float2 f23 = __half22float2(s23);
        float slog2 = f01.x * __log2f(f01.x) + f01.y * __log2f(f01.y) +
                      f23.x * __log2f(f23.x) + f23.y * __log2f(f23.y);
        float hsum = __uint_as_float(wi & 0xFFFF0000u) +
                     __uint_as_float(wj & 0xFFFF0000u);
        js  = fmaf(msk, hsum - slog2, js);    // HLN2F applied in kF
        cnt += msk;
    }

    g_js_part [blockIdx.x * 1024 + tid] = js;   // coalesced
    g_cnt_part[blockIdx.x * 1024 + tid] = cnt;
}

// ============================================================================
// kF: 32 blocks x 1024. Row-striped pair reduction + r2 + CE via deterministic
//     integer atomics; last-done block computes evo combine + output + reset.
// ============================================================================
__global__ void __launch_bounds__(1024) kF(const float* __restrict__ yevo,
                                           float* __restrict__ out)
{
    const int tid  = threadIdx.x;
    const int w    = tid >> 5;
    const int lane = tid & 31;
    const int bid  = blockIdx.x;

    __shared__ int   s_nm[8];
    __shared__ float s_red[2][32];
    __shared__ int   s_last;

    // (a) pair partials: rows bid, bid+32, ... (coalesced), one atomic per pair
    {
        float js = 0.0f, cnt = 0.0f;
        for (int r = bid; r < NB; r += 32) {
            js  += g_js_part [r * 1024 + tid];
            cnt += g_cnt_part[r * 1024 + tid];
        }
        atomicAdd((unsigned long long*)&g_js_acc[tid],
                  (unsigned long long)(long long)(js * SCALE_JS));
        atomicAdd(&g_cnt_acc[tid], (int)cnt);        // counts are exact floats
    }

    // (b) nm totals (each block computes its own copy; cheap)
    if (w < 8) {
        int nm = 0;
        for (int b = lane; b < NB; b += 32) nm += g_nm_part[b * 8 + w];
#pragma unroll
        for (int o = 16; o > 0; o >>= 1) nm += __shfl_xor_sync(0xFFFFFFFFu, nm, o);
        if (lane == 0) s_nm[w] = nm;
    }
    __syncthreads();

    // (c) r2 slice over (locus, group)
    float r2acc = 0.0f;
#pragma unroll 4
    for (int idx = bid * 1024 + tid; idx < L_ * 8; idx += 32768) {
        int g = idx & 7;
        float cntg = fmaxf(4.0f * (float)s_nm[g], 1.0f);
        unsigned char pk = g_altp[idx];
        float alt = (float)(pk & 15);
        bool nonmiss = (pk & 16) != 0;
        float af2 = nonmiss ? (alt / cntg) : 0.5f;
        if (nonmiss && af2 != 0.0f && af2 != 1.0f) {
            float den = fmaxf(af2 * (1.0f - af2), 0.01f);
            float dd  = g_pred[idx] - af2;
            r2acc += dd * dd / den;
        }
    }

    // (d) CE slice
    float ceacc = 0.0f;
    for (int idx = bid * 1024 + tid; idx < NB * 32; idx += 32768)
        ceacc += g_ce_part[idx];

    // block-reduce r2 + ce -> one atomic each
#pragma unroll
    for (int o = 16; o > 0; o >>= 1) {
        r2acc += __shfl_xor_sync(0xFFFFFFFFu, r2acc, o);
        ceacc += __shfl_xor_sync(0xFFFFFFFFu, ceacc, o);
    }
    if (lane == 0) { s_red[0][w] = r2acc; s_red[1][w] = ceacc; }
    __syncthreads();
    if (tid == 0) {
        float r2 = 0.0f, ce = 0.0f;
#pragma unroll
        for (int k = 0; k < 32; ++k) { r2 += s_red[0][k]; ce += s_red[1][k]; }
        atomicAdd((unsigned long long*)&g_r2_acc,
                  (unsigned long long)(long long)(r2 * SCALE_S));
        atomicAdd((unsigned long long*)&g_ce_acc,
                  (unsigned long long)(long long)(ce * SCALE_S));
    }

    // completion protocol
    __threadfence();
    __syncthreads();
    if (tid == 0) s_last = (atomicAdd(&g_done, 1u) == 31u);
    __syncthreads();
    if (!s_last) return;
    __threadfence();

    // ---- last block: evo combine + output + reset ----
    __shared__ float s_j[1024];
    __shared__ int   s_c[1024];
    s_j[tid] = (float)((double)g_js_acc[tid] * ISCALE_JS);
    s_c[tid] = g_cnt_acc[tid];
    __syncthreads();
    const int tT = lane * 32 + w;                    // transpose
    float jsv = HLN2F * (s_j[tid] + s_j[tT]) /
                fmaxf((float)(s_c[tid] + s_c[tT]), 1.0f);
    float wgt = __expf(-yevo[tid]);
    float rs = wgt;
#pragma unroll
    for (int o = 16; o > 0; o >>= 1) rs += __shfl_xor_sync(0xFFFFFFFFu, rs, o);
    float term = (wgt / (rs + 1e-8f)) * jsv;
#pragma unroll
    for (int o = 16; o > 0; o >>= 1) term += __shfl_xor_sync(0xFFFFFFFFu, term, o);
    __syncthreads();
    if (lane == 0) s_red[0][w] = term;
    __syncthreads();
    if (tid == 0) {
        float evo = 0.0f;
#pragma unroll
        for (int k = 0; k < 32; ++k) evo += s_red[0][k];
        float ce = (float)((double)g_ce_acc * ISCALE_S);
        float r2 = (float)((double)g_r2_acc * ISCALE_S);
        if (!isfinite(evo)) evo = 0.0f;
        out[0] = ce - 0.125f * r2 + evo;   // r2_loss = -sum*GS/B
    }

    // reset accumulators for the next graph replay
    __syncthreads();
    g_js_acc[tid] = 0ll;
    g_cnt_acc[tid] = 0;
    if (tid == 0) { g_ce_acc = 0ll; g_r2_acc = 0ll; g_done = 0u; }
}

extern "C" void kernel_launch(void* const* d_in, const int* in_sizes, int n_in,
                              void* d_out, int out_size)
{
    const float* logits = (const float*)d_in[0];
    const float* prob   = (const float*)d_in[1];
    const float* ytrue  = (const float*)d_in[2];
    const float* yevo   = (const float*)d_in[3];

    k2_mega<<<NB, 1024>>>((const float4*)logits, (const float4*)prob, ytrue);
    kF     <<<32, 1024>>>(yevo, (float*)d_out);
}